// round 5
// baseline (speedup 1.0000x reference)
#include <cuda_runtime.h>

// CustomLinearRNN: h_t = A4 h_{t-1} + A3 x_t ; known_t = A1 x_t + A2 h_{t-1}
// x:[T,K,B], h0:[H,B], A1:[K,K], A2:[K,H], A3:[H,K], A4:[H,H] (all f32)
// out: known_seq [T,K,B] then hidden_seq [T,H,B]
//
// One CTA per batch column. Ring of v_t = [x_t ; h_{t-1}] (depth 4, sliced
// layout). 16 h-warps compute h_t (4-way split dot + 2 shfl); 8 k-warps
// compute known_{t-1} concurrently (decoupled, one step behind); 64 of the
// k-threads also prefetch x_{t+1}. ONE __syncthreads per step.

#define T_STEPS 4096
#define KDIM 64
#define HDIM 128
#define BDIM 128
#define NTHREADS 768
#define SLICE 48
#define SLICEPAD 56
#define SLOTF (4 * SLICEPAD)   // 224 floats per ring slot

typedef unsigned long long u64;

__device__ __forceinline__ u64 ffma2(u64 a, u64 b, u64 c) {
    u64 d; asm("fma.rn.f32x2 %0, %1, %2, %3;" : "=l"(d) : "l"(a), "l"(b), "l"(c));
    return d;
}
__device__ __forceinline__ u64 fadd2(u64 a, u64 b) {
    u64 d; asm("add.rn.f32x2 %0, %1, %2;" : "=l"(d) : "l"(a), "l"(b));
    return d;
}
__device__ __forceinline__ u64 pk2(float lo, float hi) {
    u64 u; asm("mov.b64 %0, {%1, %2};" : "=l"(u) : "f"(lo), "f"(hi)); return u;
}
__device__ __forceinline__ void upk2(float& lo, float& hi, u64 u) {
    asm("mov.b64 {%0, %1}, %2;" : "=f"(lo), "=f"(hi) : "l"(u));
}

// logical v index -> padded sliced smem index
__device__ __forceinline__ int vidx(int i) {
    return (i / SLICE) * SLICEPAD + (i % SLICE);
}

__global__ __launch_bounds__(NTHREADS, 1)
void rnn_seq_kernel(const float* __restrict__ x,
                    const float* __restrict__ h0,
                    const float* __restrict__ A1,
                    const float* __restrict__ A2,
                    const float* __restrict__ A3,
                    const float* __restrict__ A4,
                    float* __restrict__ out_known,
                    float* __restrict__ out_hidden)
{
    __shared__ __align__(16) float vs[4][SLOTF];

    const int b    = blockIdx.x;
    const int tid  = threadIdx.x;
    const int warp = tid >> 5;
    const int lane = tid & 31;
    const int sub  = lane & 7;   // row-within-group
    const int q    = lane >> 3;  // dot quarter (48 elems each)

    const bool isH = (warp < 16);
    const int  row = isH ? (warp * 8 + sub) : ((warp - 16) * 8 + sub);

    // ---- register-resident packed weights: 24 x f32x2 per thread ----
    u64 w2[24];
    #pragma unroll
    for (int i = 0; i < 24; i++) {
        const int J = q * SLICE + 2 * i;   // J even; pair never straddles K/H split
        float wa, wb;
        if (isH) {
            if (J < KDIM) { wa = A3[row * KDIM + J];         wb = A3[row * KDIM + J + 1]; }
            else          { wa = A4[row * HDIM + (J - KDIM)]; wb = A4[row * HDIM + (J - KDIM) + 1]; }
        } else {
            if (J < KDIM) { wa = A1[row * KDIM + J];         wb = A1[row * KDIM + J + 1]; }
            else          { wa = A2[row * HDIM + (J - KDIM)]; wb = A2[row * HDIM + (J - KDIM) + 1]; }
        }
        w2[i] = pk2(wa, wb);
    }

    // ---- init ring slot 0 with v_0 = [x_0 ; h_init] ----
    if (tid < KDIM)              vs[0][vidx(tid)]        = x[(size_t)tid * BDIM + b];
    else if (tid < KDIM + HDIM)  vs[0][vidx(tid)]        = h0[(size_t)(tid - KDIM) * BDIM + b];
    __syncthreads();

    const bool isPre = (tid >= 512 && tid < 512 + KDIM);
    const int  prek  = tid - 512;

    #pragma unroll 1
    for (int t = 0; t <= T_STEPS; t++) {
        // prefetch x_{t+1} (fire LDG first; latency hides under the dots)
        float xr = 0.0f;
        if (isPre && (t + 1) < T_STEPS)
            xr = x[((size_t)(t + 1) * KDIM + prek) * BDIM + b];

        // h-warps work on step t (need t < T); k-warps on step t-1 (need t >= 1)
        const bool active = isH ? (t < T_STEPS) : (t >= 1);
        float s = 0.0f;
        if (active) {
            const int slot = isH ? (t & 3) : ((t - 1) & 3);
            const ulonglong2* vp =
                reinterpret_cast<const ulonglong2*>(&vs[slot][q * SLICEPAD]);
            u64 a0 = 0ull, a1 = 0ull, a2 = 0ull, a3 = 0ull;
            #pragma unroll
            for (int i = 0; i < 6; i++) {
                ulonglong2 p0 = vp[2 * i];
                ulonglong2 p1 = vp[2 * i + 1];
                a0 = ffma2(w2[4 * i + 0], p0.x, a0);
                a1 = ffma2(w2[4 * i + 1], p0.y, a1);
                a2 = ffma2(w2[4 * i + 2], p1.x, a2);
                a3 = ffma2(w2[4 * i + 3], p1.y, a3);
            }
            const u64 aa = fadd2(fadd2(a0, a1), fadd2(a2, a3));
            float lo, hi; upk2(lo, hi, aa);
            s = lo + hi;
        }
        // reduce the 4 quarters (lanes l, l+8, l+16, l+24)
        s += __shfl_xor_sync(0xffffffffu, s, 8);
        s += __shfl_xor_sync(0xffffffffu, s, 16);

        if (active && q == 0) {
            if (isH) {
                vs[(t + 1) & 3][vidx(KDIM + row)] = s;   // h_t for v_{t+1}
                out_hidden[(size_t)t * (HDIM * BDIM) + (size_t)row * BDIM + b] = s;
            } else {
                out_known[(size_t)(t - 1) * (KDIM * BDIM) + (size_t)row * BDIM + b] = s;
            }
        }
        if (isPre && (t + 1) < T_STEPS)
            vs[(t + 1) & 3][vidx(prek)] = xr;            // x_{t+1} for v_{t+1}

        __syncthreads();
    }
}

extern "C" void kernel_launch(void* const* d_in, const int* in_sizes, int n_in,
                              void* d_out, int out_size)
{
    const float* x  = (const float*)d_in[0];  // [T,K,B]
    const float* h0 = (const float*)d_in[1];  // [H,B]
    const float* A1 = (const float*)d_in[2];  // [K,K]
    const float* A2 = (const float*)d_in[3];  // [K,H]
    const float* A3 = (const float*)d_in[4];  // [H,K]
    const float* A4 = (const float*)d_in[5];  // [H,H]

    float* out_known  = (float*)d_out;                                   // [T,K,B]
    float* out_hidden = (float*)d_out + (size_t)T_STEPS * KDIM * BDIM;   // [T,H,B]

    rnn_seq_kernel<<<BDIM, NTHREADS>>>(x, h0, A1, A2, A3, A4,
                                       out_known, out_hidden);
    (void)in_sizes; (void)n_in; (void)out_size;
}

// round 6
// speedup vs baseline: 1.7644x; 1.7644x over previous
#include <cuda_runtime.h>

// CustomLinearRNN via chunked parallel scan.
// h_t = A4 h_{t-1} + A3 x_t ; known_t = A1 x_t + A2 h_{t-1}
// Chunks of C=32: s_i = h_{iC-1}.
//  K1 : U=A3X, Z=A1X (parallel)
//  Ksq: P = A4^32 (5 squarings)
//  K2 : per-chunk zero-state scan -> W_i (parallel over chunks)
//  K3 : boundary scan s_{i+1} = P s_i + W_i (128 sequential steps)
//  K4 : rerun chunks from s_i, fused known output (parallel over chunks)

#define T_STEPS 4096
#define KDIM 64
#define HDIM 128
#define BDIM 128
#define CHUNK 32
#define NCHUNK 128

typedef unsigned long long u64;

__device__ float g_U[(size_t)T_STEPS * HDIM * BDIM];   // A3 x_t
__device__ float g_Z[(size_t)T_STEPS * KDIM * BDIM];   // A1 x_t
__device__ float g_W[(size_t)NCHUNK * HDIM * BDIM];    // zero-state chunk ends
__device__ float g_S[(size_t)NCHUNK * HDIM * BDIM];    // boundary states
__device__ float g_Pa[HDIM * HDIM];
__device__ float g_Pb[HDIM * HDIM];

__device__ __forceinline__ u64 ffma2(u64 a, u64 b, u64 c) {
    u64 d; asm("fma.rn.f32x2 %0, %1, %2, %3;" : "=l"(d) : "l"(a), "l"(b), "l"(c));
    return d;
}
__device__ __forceinline__ u64 fadd2(u64 a, u64 b) {
    u64 d; asm("add.rn.f32x2 %0, %1, %2;" : "=l"(d) : "l"(a), "l"(b));
    return d;
}
__device__ __forceinline__ u64 pk2s(float v) {
    u64 u; asm("mov.b64 %0, {%1, %1};" : "=l"(u) : "f"(v)); return u;
}
__device__ __forceinline__ void upk2(float& lo, float& hi, u64 u) {
    asm("mov.b64 {%0, %1}, %2;" : "=f"(lo), "=f"(hi) : "l"(u));
}

// ---------------- K1: U = A3 X, Z = A1 X (one CTA per t) ----------------
__global__ __launch_bounds__(256, 1)
void k1_ux(const float* __restrict__ x,
           const float* __restrict__ A3,
           const float* __restrict__ A1)
{
    extern __shared__ float sm[];
    float* sWt = sm;               // [kk 64][192] transposed stacked [A3;A1]
    float* sX  = sm + 64 * 192;    // [kk 64][128]

    const int t   = blockIdx.x;
    const int tid = threadIdx.x;

    for (int idx = tid; idx < 192 * 64; idx += 256) {
        const int r = idx / 64, kk = idx % 64;
        sWt[kk * 192 + r] = (r < HDIM) ? A3[r * KDIM + kk]
                                       : A1[(r - HDIM) * KDIM + kk];
    }
    {
        const float4* xs = (const float4*)(x + (size_t)t * KDIM * BDIM);
        for (int idx = tid; idx < 64 * 128 / 4; idx += 256)
            ((float4*)sX)[idx] = xs[idx];
    }
    __syncthreads();

    const int ty = tid >> 4, tx = tid & 15;
    const int ru = ty * 8;    // 8 U rows
    const int rz = ty * 4;    // 4 Z rows
    const int c0 = tx * 8;    // 8 cols

    u64 accU[4][8], accZ[2][8];
    #pragma unroll
    for (int m = 0; m < 4; m++)
        #pragma unroll
        for (int j = 0; j < 8; j++) accU[m][j] = 0ull;
    #pragma unroll
    for (int m = 0; m < 2; m++)
        #pragma unroll
        for (int j = 0; j < 8; j++) accZ[m][j] = 0ull;

    #pragma unroll 4
    for (int kk = 0; kk < 64; kk++) {
        const u64* au = (const u64*)&sWt[kk * 192 + ru];
        const u64* az = (const u64*)&sWt[kk * 192 + 128 + rz];
        u64 a2u[4] = {au[0], au[1], au[2], au[3]};
        u64 a2z[2] = {az[0], az[1]};
        const float* xp = &sX[kk * 128 + c0];
        u64 x2[8];
        #pragma unroll
        for (int j = 0; j < 8; j++) x2[j] = pk2s(xp[j]);
        #pragma unroll
        for (int m = 0; m < 4; m++)
            #pragma unroll
            for (int j = 0; j < 8; j++)
                accU[m][j] = ffma2(a2u[m], x2[j], accU[m][j]);
        #pragma unroll
        for (int m = 0; m < 2; m++)
            #pragma unroll
            for (int j = 0; j < 8; j++)
                accZ[m][j] = ffma2(a2z[m], x2[j], accZ[m][j]);
    }

    #pragma unroll
    for (int m = 0; m < 4; m++) {
        float lo[8], hi[8];
        #pragma unroll
        for (int j = 0; j < 8; j++) upk2(lo[j], hi[j], accU[m][j]);
        float* d0 = &g_U[((size_t)t * HDIM + ru + 2 * m) * BDIM + c0];
        float* d1 = &g_U[((size_t)t * HDIM + ru + 2 * m + 1) * BDIM + c0];
        ((float4*)d0)[0] = make_float4(lo[0], lo[1], lo[2], lo[3]);
        ((float4*)d0)[1] = make_float4(lo[4], lo[5], lo[6], lo[7]);
        ((float4*)d1)[0] = make_float4(hi[0], hi[1], hi[2], hi[3]);
        ((float4*)d1)[1] = make_float4(hi[4], hi[5], hi[6], hi[7]);
    }
    #pragma unroll
    for (int m = 0; m < 2; m++) {
        float lo[8], hi[8];
        #pragma unroll
        for (int j = 0; j < 8; j++) upk2(lo[j], hi[j], accZ[m][j]);
        float* d0 = &g_Z[((size_t)t * KDIM + rz + 2 * m) * BDIM + c0];
        float* d1 = &g_Z[((size_t)t * KDIM + rz + 2 * m + 1) * BDIM + c0];
        ((float4*)d0)[0] = make_float4(lo[0], lo[1], lo[2], lo[3]);
        ((float4*)d0)[1] = make_float4(lo[4], lo[5], lo[6], lo[7]);
        ((float4*)d1)[0] = make_float4(hi[0], hi[1], hi[2], hi[3]);
        ((float4*)d1)[1] = make_float4(hi[4], hi[5], hi[6], hi[7]);
    }
}

// ---------------- Ksq: dst = src * src (128x128) ----------------
__global__ __launch_bounds__(128, 1)
void k_sq(const float* __restrict__ src, float* __restrict__ dst)
{
    __shared__ float row[HDIM];
    const int r = blockIdx.x, c = threadIdx.x;
    row[c] = src[r * HDIM + c];
    __syncthreads();
    float a0 = 0, a1 = 0, a2 = 0, a3 = 0;
    #pragma unroll 8
    for (int k = 0; k < HDIM; k += 4) {
        a0 = fmaf(row[k],     src[(k)     * HDIM + c], a0);
        a1 = fmaf(row[k + 1], src[(k + 1) * HDIM + c], a1);
        a2 = fmaf(row[k + 2], src[(k + 2) * HDIM + c], a2);
        a3 = fmaf(row[k + 3], src[(k + 3) * HDIM + c], a3);
    }
    dst[r * HDIM + c] = (a0 + a1) + (a2 + a3);
}

// ---------------- K2: zero-state chunk scan -> g_W ----------------
__global__ __launch_bounds__(256, 1)
void k2_chunkzero(const float* __restrict__ A4)
{
    extern __shared__ float sm[];
    float* sA4t = sm;              // [kk 128][128 r] transposed
    float* sH   = sm + 128 * 128;  // [2][kk 128][64]

    const int bi = blockIdx.x;
    const int ic = bi >> 1;
    const int bh = bi & 1;
    const int tid = threadIdx.x;
    const int ty = tid >> 4, tx = tid & 15;
    const int r0 = ty * 8;
    const int cl = tx * 4;
    const int cg = bh * 64 + cl;

    for (int idx = tid; idx < 128 * 128; idx += 256) {
        const int r = idx >> 7, kk = idx & 127;
        sA4t[kk * 128 + r] = A4[idx];
    }
    for (int idx = tid; idx < 128 * 64; idx += 256) sH[idx] = 0.0f;
    __syncthreads();

    #pragma unroll 1
    for (int c = 0; c < CHUNK; c++) {
        const int t = ic * CHUNK + c;
        const float* sHc = sH + (c & 1) * 8192;
        float*       sHn = sH + ((c + 1) & 1) * 8192;

        float4 uq[8];
        #pragma unroll
        for (int m = 0; m < 8; m++)
            uq[m] = *(const float4*)&g_U[((size_t)t * HDIM + r0 + m) * BDIM + cg];

        u64 acc[4][4];
        #pragma unroll
        for (int m = 0; m < 4; m++)
            #pragma unroll
            for (int j = 0; j < 4; j++) acc[m][j] = 0ull;

        #pragma unroll 4
        for (int kk = 0; kk < 128; kk++) {
            const u64* ap = (const u64*)&sA4t[kk * 128 + r0];
            u64 a2[4] = {ap[0], ap[1], ap[2], ap[3]};
            const float* hp = &sHc[kk * 64 + cl];
            u64 h2[4] = {pk2s(hp[0]), pk2s(hp[1]), pk2s(hp[2]), pk2s(hp[3])};
            #pragma unroll
            for (int m = 0; m < 4; m++)
                #pragma unroll
                for (int j = 0; j < 4; j++)
                    acc[m][j] = ffma2(a2[m], h2[j], acc[m][j]);
        }

        float hn[8][4];
        #pragma unroll
        for (int m = 0; m < 4; m++) {
            #pragma unroll
            for (int j = 0; j < 4; j++) {
                float lo, hi; upk2(lo, hi, acc[m][j]);
                hn[2 * m][j]     = lo + ((const float*)&uq[2 * m])[j];
                hn[2 * m + 1][j] = hi + ((const float*)&uq[2 * m + 1])[j];
            }
        }

        if (c == CHUNK - 1) {
            #pragma unroll
            for (int rr = 0; rr < 8; rr++)
                *(float4*)&g_W[((size_t)ic * HDIM + r0 + rr) * BDIM + cg] =
                    make_float4(hn[rr][0], hn[rr][1], hn[rr][2], hn[rr][3]);
        } else {
            #pragma unroll
            for (int rr = 0; rr < 8; rr++)
                *(float4*)&sHn[(r0 + rr) * 64 + cl] =
                    make_float4(hn[rr][0], hn[rr][1], hn[rr][2], hn[rr][3]);
        }
        __syncthreads();
    }
}

// ---------------- K3: boundary scan, one CTA per b ----------------
__global__ __launch_bounds__(128, 1)
void k3_scan(const float* __restrict__ h0)
{
    extern __shared__ float sm[];
    float* sP = sm;                 // [r][130] padded
    float* sS = sm + 128 * 130;

    const int b = blockIdx.x;
    const int tid = threadIdx.x;

    for (int idx = tid; idx < 128 * 128; idx += 128) {
        const int r = idx >> 7, kk = idx & 127;
        sP[r * 130 + kk] = g_Pa[idx];
    }
    float s = h0[tid * BDIM + b];
    sS[tid] = s;
    __syncthreads();

    #pragma unroll 1
    for (int i = 0; i < NCHUNK; i++) {
        g_S[((size_t)i * HDIM + tid) * BDIM + b] = s;
        const float w = g_W[((size_t)i * HDIM + tid) * BDIM + b];
        const u64* s2 = (const u64*)sS;
        const u64* p2 = (const u64*)&sP[tid * 130];
        u64 a0 = 0ull, a1 = 0ull, a2 = 0ull, a3 = 0ull;
        #pragma unroll 4
        for (int m = 0; m < 64; m += 4) {
            a0 = ffma2(p2[m],     s2[m],     a0);
            a1 = ffma2(p2[m + 1], s2[m + 1], a1);
            a2 = ffma2(p2[m + 2], s2[m + 2], a2);
            a3 = ffma2(p2[m + 3], s2[m + 3], a3);
        }
        const u64 aa = fadd2(fadd2(a0, a1), fadd2(a2, a3));
        float lo, hi; upk2(lo, hi, aa);
        s = lo + hi + w;
        __syncthreads();
        sS[tid] = s;
        __syncthreads();
    }
}

// ---------------- K4: rerun chunks + fused known ----------------
__global__ __launch_bounds__(256, 1)
void k4_final(const float* __restrict__ A4,
              const float* __restrict__ A2,
              float* __restrict__ out_known,
              float* __restrict__ out_hidden)
{
    extern __shared__ float sm[];
    float* sWt = sm;               // [kk 128][192]: r<128 A4t, r>=128 A2t
    float* sH  = sm + 128 * 192;   // [2][kk 128][64]

    const int bi = blockIdx.x;
    const int ic = bi >> 1;
    const int bh = bi & 1;
    const int tid = threadIdx.x;
    const int ty = tid >> 4, tx = tid & 15;
    const int r0  = ty * 8;   // h rows
    const int rk0 = ty * 4;   // known rows
    const int cl = tx * 4;
    const int cg = bh * 64 + cl;

    for (int idx = tid; idx < 192 * 128; idx += 256) {
        const int r = idx >> 7, kk = idx & 127;
        sWt[kk * 192 + r] = (r < HDIM) ? A4[r * HDIM + kk]
                                       : A2[(r - HDIM) * HDIM + kk];
    }
    for (int idx = tid; idx < 128 * 64; idx += 256) {
        const int kk = idx >> 6, cc = idx & 63;
        sH[idx] = g_S[((size_t)ic * HDIM + kk) * BDIM + bh * 64 + cc];
    }
    __syncthreads();

    #pragma unroll 1
    for (int c = 0; c < CHUNK; c++) {
        const int t = ic * CHUNK + c;
        const float* sHc = sH + (c & 1) * 8192;
        float*       sHn = sH + ((c + 1) & 1) * 8192;

        float4 uq[8], zq[4];
        #pragma unroll
        for (int m = 0; m < 8; m++)
            uq[m] = *(const float4*)&g_U[((size_t)t * HDIM + r0 + m) * BDIM + cg];
        #pragma unroll
        for (int m = 0; m < 4; m++)
            zq[m] = *(const float4*)&g_Z[((size_t)t * KDIM + rk0 + m) * BDIM + cg];

        u64 acch[4][4], acck[2][4];
        #pragma unroll
        for (int m = 0; m < 4; m++)
            #pragma unroll
            for (int j = 0; j < 4; j++) acch[m][j] = 0ull;
        #pragma unroll
        for (int m = 0; m < 2; m++)
            #pragma unroll
            for (int j = 0; j < 4; j++) acck[m][j] = 0ull;

        #pragma unroll 4
        for (int kk = 0; kk < 128; kk++) {
            const u64* ah = (const u64*)&sWt[kk * 192 + r0];
            const u64* ak = (const u64*)&sWt[kk * 192 + 128 + rk0];
            u64 a2h[4] = {ah[0], ah[1], ah[2], ah[3]};
            u64 a2k[2] = {ak[0], ak[1]};
            const float* hp = &sHc[kk * 64 + cl];
            u64 h2[4] = {pk2s(hp[0]), pk2s(hp[1]), pk2s(hp[2]), pk2s(hp[3])};
            #pragma unroll
            for (int m = 0; m < 4; m++)
                #pragma unroll
                for (int j = 0; j < 4; j++)
                    acch[m][j] = ffma2(a2h[m], h2[j], acch[m][j]);
            #pragma unroll
            for (int m = 0; m < 2; m++)
                #pragma unroll
                for (int j = 0; j < 4; j++)
                    acck[m][j] = ffma2(a2k[m], h2[j], acck[m][j]);
        }

        // known_t = Z_t + A2 h_{t-1}
        #pragma unroll
        for (int m = 0; m < 2; m++) {
            float lo[4], hi[4];
            #pragma unroll
            for (int j = 0; j < 4; j++) upk2(lo[j], hi[j], acck[m][j]);
            const float* z0 = (const float*)&zq[2 * m];
            const float* z1 = (const float*)&zq[2 * m + 1];
            *(float4*)&out_known[((size_t)t * KDIM + rk0 + 2 * m) * BDIM + cg] =
                make_float4(lo[0] + z0[0], lo[1] + z0[1], lo[2] + z0[2], lo[3] + z0[3]);
            *(float4*)&out_known[((size_t)t * KDIM + rk0 + 2 * m + 1) * BDIM + cg] =
                make_float4(hi[0] + z1[0], hi[1] + z1[1], hi[2] + z1[2], hi[3] + z1[3]);
        }

        // h_t = A4 h_{t-1} + u_t
        float hn[8][4];
        #pragma unroll
        for (int m = 0; m < 4; m++) {
            #pragma unroll
            for (int j = 0; j < 4; j++) {
                float lo, hi; upk2(lo, hi, acch[m][j]);
                hn[2 * m][j]     = lo + ((const float*)&uq[2 * m])[j];
                hn[2 * m + 1][j] = hi + ((const float*)&uq[2 * m + 1])[j];
            }
        }
        #pragma unroll
        for (int rr = 0; rr < 8; rr++) {
            const float4 v = make_float4(hn[rr][0], hn[rr][1], hn[rr][2], hn[rr][3]);
            *(float4*)&out_hidden[((size_t)t * HDIM + r0 + rr) * BDIM + cg] = v;
            *(float4*)&sHn[(r0 + rr) * 64 + cl] = v;
        }
        __syncthreads();
    }
}

// ---------------- host ----------------
extern "C" void kernel_launch(void* const* d_in, const int* in_sizes, int n_in,
                              void* d_out, int out_size)
{
    const float* x  = (const float*)d_in[0];
    const float* h0 = (const float*)d_in[1];
    const float* A1 = (const float*)d_in[2];
    const float* A2 = (const float*)d_in[3];
    const float* A3 = (const float*)d_in[4];
    const float* A4 = (const float*)d_in[5];

    float* out_known  = (float*)d_out;
    float* out_hidden = (float*)d_out + (size_t)T_STEPS * KDIM * BDIM;

    const int smem1 = (64 * 192 + 64 * 128) * 4;           // 81920
    const int smem2 = (128 * 128 + 2 * 128 * 64) * 4;      // 131072
    const int smem3 = (128 * 130 + 128) * 4;               // 67072
    const int smem4 = (128 * 192 + 2 * 128 * 64) * 4;      // 163840

    cudaFuncSetAttribute(k1_ux,       cudaFuncAttributeMaxDynamicSharedMemorySize, smem1);
    cudaFuncSetAttribute(k2_chunkzero,cudaFuncAttributeMaxDynamicSharedMemorySize, smem2);
    cudaFuncSetAttribute(k3_scan,     cudaFuncAttributeMaxDynamicSharedMemorySize, smem3);
    cudaFuncSetAttribute(k4_final,    cudaFuncAttributeMaxDynamicSharedMemorySize, smem4);

    float *pa, *pb;
    cudaGetSymbolAddress((void**)&pa, g_Pa);
    cudaGetSymbolAddress((void**)&pb, g_Pb);

    k1_ux<<<T_STEPS, 256, smem1>>>(x, A3, A1);

    k_sq<<<HDIM, HDIM>>>(A4, pa);   // A4^2
    k_sq<<<HDIM, HDIM>>>(pa, pb);   // A4^4
    k_sq<<<HDIM, HDIM>>>(pb, pa);   // A4^8
    k_sq<<<HDIM, HDIM>>>(pa, pb);   // A4^16
    k_sq<<<HDIM, HDIM>>>(pb, pa);   // A4^32 -> g_Pa

    k2_chunkzero<<<2 * NCHUNK, 256, smem2>>>(A4);
    k3_scan<<<BDIM, 128, smem3>>>(h0);
    k4_final<<<2 * NCHUNK, 256, smem4>>>(A4, A2, out_known, out_hidden);

    (void)in_sizes; (void)n_in; (void)out_size;
}